// round 1
// baseline (speedup 1.0000x reference)
#include <cuda_runtime.h>
#include <math.h>

// Problem constants (fixed by setup_inputs)
#define NH   8          // NUM_KV_HEADS
#define HD   128        // HEAD_DIM
#define BSZ  16         // BLOCK_SIZE
#define NPAST 4095      // past tokens: 255 full blocks * 16 + rem 15
#define POSQ  4095      // MODEL_CONTEXT_LEN - 1
#define NPOS  4096      // rope table rows (0..4095)
#define SPLITS 16
#define TOKS_PER_SPLIT 256   // 16 * 256 = 4096 >= 4095
#define SCALE 0.08838834764831845f   // 1/sqrt(128)
#define MAXB 8
#define SSTRIDE 136     // floats per partial: [0]=m [1]=l [8..135]=acc, 16B-aligned

// Scratch (no cudaMalloc allowed)
__device__ float2 g_rope[NPOS * 64];                       // 2 MB cos/sin table
__device__ float  g_scratch[MAXB * NH * SPLITS * SSTRIDE]; // split partials

// ---------------------------------------------------------------------------
// 1) RoPE table: g_rope[pos*64+f] = (cos(pos*invf), sin(pos*invf))
//    invf = 10000^(-f/64) = exp2(-f * log2(10000)/64)
// ---------------------------------------------------------------------------
__global__ void rope_table_kernel() {
    int idx = blockIdx.x * blockDim.x + threadIdx.x;
    if (idx >= NPOS * 64) return;
    int pos = idx >> 6;
    int f   = idx & 63;
    float inv = exp2f(-(float)f * (float)(13.287712379549449 / 64.0));
    float ang = (float)pos * inv;
    float s, c;
    sincosf(ang, &s, &c);   // accurate variant (Payne-Hanek range reduction)
    g_rope[idx] = make_float2(c, s);
}

// ---------------------------------------------------------------------------
// 2) Split attention: one CTA per (b, h, split). 256 threads = 8 warps.
//    Each warp processes whole tokens (stride 8). Lane holds dims 4L..4L+3.
//    RoPE pair (d, d+64) exchanged via shfl_xor(16).
// ---------------------------------------------------------------------------
__global__ __launch_bounds__(256) void attn_split_kernel(
    const float* __restrict__ q,
    const float* __restrict__ kcache,
    const float* __restrict__ vcache,
    const int*   __restrict__ btab,
    int blocks_per_seq)
{
    int bid  = blockIdx.x;
    int s    = bid % SPLITS;
    int bh   = bid / SPLITS;
    int h    = bh % NH, b = bh / NH;
    int tid  = threadIdx.x, lane = tid & 31, warp = tid >> 5;
    int j4   = lane * 4;
    int f4   = 4 * (lane & 15);             // freq base (same for lane and lane^16)
    float sgn = (lane < 16) ? -1.f : 1.f;

    // Load q, rotate at POSQ, fold in softmax scale.
    float4 qv = *(const float4*)(q + (size_t)bh * HD + j4);
    float4 qp;
    qp.x = __shfl_xor_sync(0xffffffffu, qv.x, 16);
    qp.y = __shfl_xor_sync(0xffffffffu, qv.y, 16);
    qp.z = __shfl_xor_sync(0xffffffffu, qv.z, 16);
    qp.w = __shfl_xor_sync(0xffffffffu, qv.w, 16);
    const float4* qt = (const float4*)(g_rope + POSQ * 64 + f4);
    float4 qt01 = qt[0], qt23 = qt[1];      // (c0,s0,c1,s1),(c2,s2,c3,s3)
    float4 qr;
    qr.x = (qv.x * qt01.x + sgn * qp.x * qt01.y) * SCALE;
    qr.y = (qv.y * qt01.z + sgn * qp.y * qt01.w) * SCALE;
    qr.z = (qv.z * qt23.x + sgn * qp.z * qt23.y) * SCALE;
    qr.w = (qv.w * qt23.z + sgn * qp.w * qt23.w) * SCALE;

    float  m = -1e30f, l = 0.f;
    float4 acc = make_float4(0.f, 0.f, 0.f, 0.f);

    int tEnd = min((s + 1) * TOKS_PER_SPLIT, NPAST);
    #pragma unroll 2
    for (int t = s * TOKS_PER_SPLIT + warp; t < tEnd; t += 8) {
        int blk = __ldg(btab + b * blocks_per_seq + (t >> 4));
        size_t base = ((size_t)blk * BSZ + (t & 15)) * (NH * HD) + (size_t)h * HD;
        float4 kv = *(const float4*)(kcache + base + j4);
        float4 vv = *(const float4*)(vcache + base + j4);
        const float4* tp = (const float4*)(g_rope + (size_t)t * 64 + f4);
        float4 c01 = tp[0], c23 = tp[1];

        float4 kp;
        kp.x = __shfl_xor_sync(0xffffffffu, kv.x, 16);
        kp.y = __shfl_xor_sync(0xffffffffu, kv.y, 16);
        kp.z = __shfl_xor_sync(0xffffffffu, kv.z, 16);
        kp.w = __shfl_xor_sync(0xffffffffu, kv.w, 16);

        float r0 = kv.x * c01.x + sgn * kp.x * c01.y;
        float r1 = kv.y * c01.z + sgn * kp.y * c01.w;
        float r2 = kv.z * c23.x + sgn * kp.z * c23.y;
        float r3 = kv.w * c23.z + sgn * kp.w * c23.w;

        float dot = r0 * qr.x + r1 * qr.y + r2 * qr.z + r3 * qr.w;
        #pragma unroll
        for (int off = 16; off; off >>= 1)
            dot += __shfl_xor_sync(0xffffffffu, dot, off);

        float mn   = fmaxf(m, dot);
        float corr = __expf(m - mn);
        float p    = __expf(dot - mn);
        l = l * corr + p;
        acc.x = acc.x * corr + p * vv.x;
        acc.y = acc.y * corr + p * vv.y;
        acc.z = acc.z * corr + p * vv.z;
        acc.w = acc.w * corr + p * vv.w;
        m = mn;
    }

    // Cross-warp combine in SMEM
    __shared__ float  sm_m[8], sm_l[8];
    __shared__ float4 sm_acc[8][32];
    sm_m[warp] = m; sm_l[warp] = l; sm_acc[warp][lane] = acc;
    __syncthreads();

    if (warp == 0) {
        float M = -1e30f;
        #pragma unroll
        for (int w = 0; w < 8; w++) M = fmaxf(M, sm_m[w]);
        float L = 0.f;
        float4 A = make_float4(0.f, 0.f, 0.f, 0.f);
        #pragma unroll
        for (int w = 0; w < 8; w++) {
            float e = __expf(sm_m[w] - M);
            L += e * sm_l[w];
            float4 a = sm_acc[w][lane];
            A.x += e * a.x; A.y += e * a.y; A.z += e * a.z; A.w += e * a.w;
        }
        float* out = g_scratch + (size_t)bid * SSTRIDE;
        if (lane == 0) { out[0] = M; out[1] = L; }
        *(float4*)(out + 8 + j4) = A;
    }
}

// ---------------------------------------------------------------------------
// 3) Combine: one block per (b,h). Merges SPLITS partials + current token.
// ---------------------------------------------------------------------------
__global__ __launch_bounds__(128) void attn_combine_kernel(
    const float* __restrict__ q,
    const float* __restrict__ k,
    const float* __restrict__ v,
    float* __restrict__ out)
{
    int bh = blockIdx.x;
    int d  = threadIdx.x;                 // 0..127
    int f  = d & 63;
    float sgn = (d < 64) ? -1.f : 1.f;
    float2 cs = g_rope[POSQ * 64 + f];
    size_t o = (size_t)bh * HD;

    float qd = q[o + d], qp = q[o + (d ^ 64)];
    float kd = k[o + d], kp = k[o + (d ^ 64)];
    float qr = qd * cs.x + sgn * qp * cs.y;
    float kr = kd * cs.x + sgn * kp * cs.y;

    __shared__ float red[128];
    red[d] = qr * kr;
    __syncthreads();
    for (int off = 64; off; off >>= 1) {
        if (d < off) red[d] += red[d + off];
        __syncthreads();
    }
    float score = red[0] * SCALE;         // current-token logit

    const float* sc = g_scratch + (size_t)bh * SPLITS * SSTRIDE;
    float M = score;
    #pragma unroll
    for (int s2 = 0; s2 < SPLITS; s2++) M = fmaxf(M, sc[s2 * SSTRIDE]);

    float w = __expf(score - M);
    float L = w;
    float A = w * v[o + d];
    #pragma unroll
    for (int s2 = 0; s2 < SPLITS; s2++) {
        float e = __expf(sc[s2 * SSTRIDE] - M);
        L += e * sc[s2 * SSTRIDE + 1];
        A += e * sc[s2 * SSTRIDE + 8 + d];
    }
    out[o + d] = A / L;
}

// ---------------------------------------------------------------------------
extern "C" void kernel_launch(void* const* d_in, const int* in_sizes, int n_in,
                              void* d_out, int out_size)
{
    const float* q  = (const float*)d_in[0];
    const float* k  = (const float*)d_in[1];
    const float* v  = (const float*)d_in[2];
    const float* kc = (const float*)d_in[3];
    const float* vc = (const float*)d_in[4];
    const int*   bt = (const int*)d_in[5];

    int B   = in_sizes[0] / (NH * HD);     // 8
    int bps = in_sizes[5] / B;             // 256 blocks per sequence

    rope_table_kernel<<<(NPOS * 64 + 255) / 256, 256>>>();
    attn_split_kernel<<<B * NH * SPLITS, 256>>>(q, kc, vc, bt, bps);
    attn_combine_kernel<<<B * NH, 128>>>(q, k, v, (float*)d_out);
}

// round 2
// speedup vs baseline: 1.0852x; 1.0852x over previous
#include <cuda_runtime.h>
#include <math.h>

// Problem constants (fixed by setup_inputs)
#define NH    8
#define HD    128
#define BSZ   16
#define NPAST 4095            // past tokens
#define POSQ  4095            // MODEL_CONTEXT_LEN - 1
#define SPLITS 16
#define TPS   256             // tokens per split (16*256 = 4096 >= 4095)
#define SCALE 0.08838834764831845f
#define SSTRIDE 136           // floats per partial: [0]=m [1]=l [8..135]=acc

__device__ float g_scratch[8 * NH * SPLITS * SSTRIDE];

// ---------------------------------------------------------------------------
// Split attention. One CTA per (b,h,split), 256 threads = 8 warps.
// Warp owns whole tokens (stride 8), lane holds dims 4L..4L+3 (float4 row).
// RoPE folded into q via relative-angle rotation recurrence: no table, no
// per-token shuffles of K. 4 tokens per body for batched loads + amortized
// softmax correction.
// ---------------------------------------------------------------------------
__global__ __launch_bounds__(256, 2) void attn_split_kernel(
    const float* __restrict__ q,
    const float* __restrict__ kcache,
    const float* __restrict__ vcache,
    const int*   __restrict__ btab,
    int bps)
{
    int bid  = blockIdx.x;
    int sp   = bid & (SPLITS - 1);
    int bh   = bid >> 4;
    int h    = bh & (NH - 1), b = bh >> 3;
    int tid  = threadIdx.x, lane = tid & 31, warp = tid >> 5;
    int j4   = lane * 4;
    float sgn = (lane < 16) ? -1.f : 1.f;

    // q (scaled) and its rope partner (dim ^ 64) via one-time shfl
    float4 qv = *(const float4*)(q + (size_t)bh * HD + j4);
    float qa0 = qv.x * SCALE, qa1 = qv.y * SCALE, qa2 = qv.z * SCALE, qa3 = qv.w * SCALE;
    float qb0 = sgn * SCALE * __shfl_xor_sync(0xffffffffu, qv.x, 16);
    float qb1 = sgn * SCALE * __shfl_xor_sync(0xffffffffu, qv.y, 16);
    float qb2 = sgn * SCALE * __shfl_xor_sync(0xffffffffu, qv.z, 16);
    float qb3 = sgn * SCALE * __shfl_xor_sync(0xffffffffu, qv.w, 16);

    // Phase init: phi = (POSQ - t0) * invf per frequency; step = -8*invf/token.
    int   t0 = sp * TPS + warp;
    float d0 = (float)(POSQ - t0);
    float pc[4], ps[4], rc[4], rs[4];
    #pragma unroll
    for (int i = 0; i < 4; i++) {
        int f = 4 * (lane & 15) + i;
        float inv = exp2f(-(float)f * (13.287712379549449f / 64.0f));
        sincosf(d0 * inv, &ps[i], &pc[i]);      // accurate range reduction
        sincosf(8.0f * inv, &rs[i], &rc[i]);    // per-step rotation constants
    }

    float  m = -1e30f, l = 0.f;
    float4 acc = make_float4(0.f, 0.f, 0.f, 0.f);

    const int    row = NH * HD;                 // 1024 floats per token record
    const int*   bt  = btab + b * bps;
    const size_t hoff = (size_t)h * HD + j4;

    int t = t0;
    #pragma unroll 1
    for (int body = 0; body < TPS / 32; body++) {
        int tA = t, tB = t + 8, tC = t + 16, tD = t + 24;
        int blkA = __ldg(bt + (tA >> 4));
        int blkB = __ldg(bt + (tB >> 4));
        int blkC = __ldg(bt + (tC >> 4));
        int blkD = __ldg(bt + (tD >> 4));
        size_t oA = ((size_t)blkA * BSZ + (tA & 15)) * row + hoff;
        size_t oB = ((size_t)blkB * BSZ + (tB & 15)) * row + hoff;
        size_t oC = ((size_t)blkC * BSZ + (tC & 15)) * row + hoff;
        size_t oD = ((size_t)blkD * BSZ + (tD & 15)) * row + hoff;
        float4 kA = *(const float4*)(kcache + oA);
        float4 kB = *(const float4*)(kcache + oB);
        float4 kC = *(const float4*)(kcache + oC);
        float4 kD = *(const float4*)(kcache + oD);
        float4 vA = *(const float4*)(vcache + oA);
        float4 vB = *(const float4*)(vcache + oB);
        float4 vC = *(const float4*)(vcache + oC);
        float4 vD = *(const float4*)(vcache + oD);

        float dA, dB, dC, dD;
        {   // token A
            float e0 = qa0 * pc[0] + qb0 * ps[0];
            float e1 = qa1 * pc[1] + qb1 * ps[1];
            float e2 = qa2 * pc[2] + qb2 * ps[2];
            float e3 = qa3 * pc[3] + qb3 * ps[3];
            dA = kA.x * e0 + kA.y * e1 + kA.z * e2 + kA.w * e3;
        }
        #pragma unroll
        for (int i = 0; i < 4; i++) { float c2 = pc[i]*rc[i] + ps[i]*rs[i];
                                      ps[i] = ps[i]*rc[i] - pc[i]*rs[i]; pc[i] = c2; }
        {   // token B
            float e0 = qa0 * pc[0] + qb0 * ps[0];
            float e1 = qa1 * pc[1] + qb1 * ps[1];
            float e2 = qa2 * pc[2] + qb2 * ps[2];
            float e3 = qa3 * pc[3] + qb3 * ps[3];
            dB = kB.x * e0 + kB.y * e1 + kB.z * e2 + kB.w * e3;
        }
        #pragma unroll
        for (int i = 0; i < 4; i++) { float c2 = pc[i]*rc[i] + ps[i]*rs[i];
                                      ps[i] = ps[i]*rc[i] - pc[i]*rs[i]; pc[i] = c2; }
        {   // token C
            float e0 = qa0 * pc[0] + qb0 * ps[0];
            float e1 = qa1 * pc[1] + qb1 * ps[1];
            float e2 = qa2 * pc[2] + qb2 * ps[2];
            float e3 = qa3 * pc[3] + qb3 * ps[3];
            dC = kC.x * e0 + kC.y * e1 + kC.z * e2 + kC.w * e3;
        }
        #pragma unroll
        for (int i = 0; i < 4; i++) { float c2 = pc[i]*rc[i] + ps[i]*rs[i];
                                      ps[i] = ps[i]*rc[i] - pc[i]*rs[i]; pc[i] = c2; }
        {   // token D
            float e0 = qa0 * pc[0] + qb0 * ps[0];
            float e1 = qa1 * pc[1] + qb1 * ps[1];
            float e2 = qa2 * pc[2] + qb2 * ps[2];
            float e3 = qa3 * pc[3] + qb3 * ps[3];
            dD = kD.x * e0 + kD.y * e1 + kD.z * e2 + kD.w * e3;
        }
        #pragma unroll
        for (int i = 0; i < 4; i++) { float c2 = pc[i]*rc[i] + ps[i]*rs[i];
                                      ps[i] = ps[i]*rc[i] - pc[i]*rs[i]; pc[i] = c2; }

        // interleaved warp reductions (independent chains)
        #pragma unroll
        for (int off = 16; off; off >>= 1) {
            dA += __shfl_xor_sync(0xffffffffu, dA, off);
            dB += __shfl_xor_sync(0xffffffffu, dB, off);
            dC += __shfl_xor_sync(0xffffffffu, dC, off);
            dD += __shfl_xor_sync(0xffffffffu, dD, off);
        }

        // mask out-of-range token (only t=4095 in last body of split 15)
        if (tA >= NPAST) dA = -1e30f;
        if (tB >= NPAST) dB = -1e30f;
        if (tC >= NPAST) dC = -1e30f;
        if (tD >= NPAST) dD = -1e30f;

        float mn   = fmaxf(fmaxf(fmaxf(dA, dB), fmaxf(dC, dD)), m);
        float corr = __expf(m - mn);
        float pA = __expf(dA - mn);
        float pB = __expf(dB - mn);
        float pC = __expf(dC - mn);
        float pD = __expf(dD - mn);
        m = mn;
        l = l * corr + (pA + pB) + (pC + pD);
        acc.x = acc.x * corr + pA * vA.x + pB * vB.x + pC * vC.x + pD * vD.x;
        acc.y = acc.y * corr + pA * vA.y + pB * vB.y + pC * vC.y + pD * vD.y;
        acc.z = acc.z * corr + pA * vA.z + pB * vB.z + pC * vC.z + pD * vD.z;
        acc.w = acc.w * corr + pA * vA.w + pB * vB.w + pC * vC.w + pD * vD.w;

        t += 32;
    }

    // cross-warp combine in SMEM
    __shared__ float  sm_m[8], sm_l[8];
    __shared__ float4 sm_acc[8][32];
    sm_m[warp] = m; sm_l[warp] = l; sm_acc[warp][lane] = acc;
    __syncthreads();

    if (warp == 0) {
        float M = -1e30f;
        #pragma unroll
        for (int w = 0; w < 8; w++) M = fmaxf(M, sm_m[w]);
        float L = 0.f;
        float4 A = make_float4(0.f, 0.f, 0.f, 0.f);
        #pragma unroll
        for (int w = 0; w < 8; w++) {
            float e = __expf(sm_m[w] - M);
            L += e * sm_l[w];
            float4 a = sm_acc[w][lane];
            A.x += e * a.x; A.y += e * a.y; A.z += e * a.z; A.w += e * a.w;
        }
        float* out = g_scratch + (size_t)bid * SSTRIDE;
        if (lane == 0) { out[0] = M; out[1] = L; }
        *(float4*)(out + 8 + j4) = A;
    }
}

// ---------------------------------------------------------------------------
// Combine: one block per (b,h). Current-token score needs NO rope:
// rope(q,p)·rope(k,p) = q·k (same-position rotations cancel).
// ---------------------------------------------------------------------------
__global__ __launch_bounds__(128) void attn_combine_kernel(
    const float* __restrict__ q,
    const float* __restrict__ k,
    const float* __restrict__ v,
    float* __restrict__ out)
{
    int bh = blockIdx.x;
    int d  = threadIdx.x;                 // 0..127
    size_t o = (size_t)bh * HD;

    __shared__ float red[128];
    red[d] = q[o + d] * k[o + d];
    __syncthreads();
    for (int off = 64; off; off >>= 1) {
        if (d < off) red[d] += red[d + off];
        __syncthreads();
    }
    float score = red[0] * SCALE;

    const float* sc = g_scratch + (size_t)bh * SPLITS * SSTRIDE;
    float M = score;
    #pragma unroll
    for (int s2 = 0; s2 < SPLITS; s2++) M = fmaxf(M, sc[s2 * SSTRIDE]);

    float w = __expf(score - M);
    float L = w;
    float A = w * v[o + d];
    #pragma unroll
    for (int s2 = 0; s2 < SPLITS; s2++) {
        float e = __expf(sc[s2 * SSTRIDE] - M);
        L += e * sc[s2 * SSTRIDE + 1];
        A += e * sc[s2 * SSTRIDE + 8 + d];
    }
    out[o + d] = A / L;
}

// ---------------------------------------------------------------------------
extern "C" void kernel_launch(void* const* d_in, const int* in_sizes, int n_in,
                              void* d_out, int out_size)
{
    const float* q  = (const float*)d_in[0];
    const float* k  = (const float*)d_in[1];
    const float* v  = (const float*)d_in[2];
    const float* kc = (const float*)d_in[3];
    const float* vc = (const float*)d_in[4];
    const int*   bt = (const int*)d_in[5];

    int B   = in_sizes[0] / (NH * HD);   // 8
    int bps = in_sizes[5] / B;           // 256

    attn_split_kernel<<<B * NH * SPLITS, 256>>>(q, kc, vc, bt, bps);
    attn_combine_kernel<<<B * NH, 128>>>(q, k, v, (float*)d_out);
}

// round 3
// speedup vs baseline: 1.2531x; 1.1547x over previous
#include <cuda_runtime.h>
#include <math.h>

#define NH    8
#define HD    128
#define BSZ   16
#define NPAST 4095
#define POSQ  4095
#define SPLITS 16
#define TPS   256
#define SCALE 0.08838834764831845f
#define SSTRIDE 136
#define NBH   64              // B * NH

__device__ float g_scratch[NBH * SPLITS * SSTRIDE];
__device__ int   g_cnt[NBH];  // zero-init; each launch returns it to zero

// ---------------------------------------------------------------------------
// Fused split + combine. One CTA per (b,h,split), 256 threads = 8 warps.
// Warp owns whole tokens (stride 8), lane holds dims 4L..4L+3 (float4 row).
// RoPE folded into q via relative-angle rotation recurrence.
// Double-buffered K/V loads (prefetch next 4-token body while computing).
// Last CTA per (b,h) (atomic counter) performs the final combine.
// ---------------------------------------------------------------------------
__global__ __launch_bounds__(256, 2) void attn_fused_kernel(
    const float* __restrict__ q,
    const float* __restrict__ kk,
    const float* __restrict__ vv,
    const float* __restrict__ kcache,
    const float* __restrict__ vcache,
    const int*   __restrict__ btab,
    float* __restrict__ out,
    int bps)
{
    int bid  = blockIdx.x;
    int sp   = bid & (SPLITS - 1);
    int bh   = bid >> 4;
    int h    = bh & (NH - 1), b = bh >> 3;
    int tid  = threadIdx.x, lane = tid & 31, warp = tid >> 5;
    int j4   = lane * 4;
    float sgn = (lane < 16) ? -1.f : 1.f;

    // q (scaled) and its rope partner (dim ^ 64) via one-time shfl
    float4 qv = *(const float4*)(q + (size_t)bh * HD + j4);
    float qa0 = qv.x * SCALE, qa1 = qv.y * SCALE, qa2 = qv.z * SCALE, qa3 = qv.w * SCALE;
    float qb0 = sgn * SCALE * __shfl_xor_sync(0xffffffffu, qv.x, 16);
    float qb1 = sgn * SCALE * __shfl_xor_sync(0xffffffffu, qv.y, 16);
    float qb2 = sgn * SCALE * __shfl_xor_sync(0xffffffffu, qv.z, 16);
    float qb3 = sgn * SCALE * __shfl_xor_sync(0xffffffffu, qv.w, 16);

    // Phase init: phi = (POSQ - t) * invf; advances by -8*invf per warp step.
    int   t0 = sp * TPS + warp;
    float d0 = (float)(POSQ - t0);
    float pc[4], ps[4], rc[4], rs[4];
    #pragma unroll
    for (int i = 0; i < 4; i++) {
        int f = 4 * (lane & 15) + i;
        float inv = exp2f(-(float)f * (13.287712379549449f / 64.0f));
        sincosf(d0 * inv, &ps[i], &pc[i]);
        sincosf(8.0f * inv, &rs[i], &rc[i]);
    }

    float  m = -1e30f, l = 0.f;
    float4 acc = make_float4(0.f, 0.f, 0.f, 0.f);

    const int    row  = NH * HD;
    const int*   bt   = btab + b * bps;
    const size_t hoff = (size_t)h * HD + j4;

    float4 kb[2][4], vb[2][4];

#define LOADB(BUF, TB) do {                                                   \
        int _tA = (TB), _tB = (TB) + 8, _tC = (TB) + 16, _tD = (TB) + 24;     \
        size_t _oA = ((size_t)__ldg(bt + (_tA >> 4)) * BSZ + (_tA & 15)) * row + hoff; \
        size_t _oB = ((size_t)__ldg(bt + (_tB >> 4)) * BSZ + (_tB & 15)) * row + hoff; \
        size_t _oC = ((size_t)__ldg(bt + (_tC >> 4)) * BSZ + (_tC & 15)) * row + hoff; \
        size_t _oD = ((size_t)__ldg(bt + (_tD >> 4)) * BSZ + (_tD & 15)) * row + hoff; \
        kb[BUF][0] = __ldcs((const float4*)(kcache + _oA));                   \
        kb[BUF][1] = __ldcs((const float4*)(kcache + _oB));                   \
        kb[BUF][2] = __ldcs((const float4*)(kcache + _oC));                   \
        kb[BUF][3] = __ldcs((const float4*)(kcache + _oD));                   \
        vb[BUF][0] = __ldcs((const float4*)(vcache + _oA));                   \
        vb[BUF][1] = __ldcs((const float4*)(vcache + _oB));                   \
        vb[BUF][2] = __ldcs((const float4*)(vcache + _oC));                   \
        vb[BUF][3] = __ldcs((const float4*)(vcache + _oD));                   \
    } while (0)

    LOADB(0, t0);

    #pragma unroll 2
    for (int body = 0; body < TPS / 32; body++) {
        int cur = body & 1;
        if (body + 1 < TPS / 32) LOADB(1 - cur, t0 + (body + 1) * 32);

        int tA = t0 + body * 32;
        float dot[4];
        #pragma unroll
        for (int g = 0; g < 4; g++) {
            float e0 = qa0 * pc[0] + qb0 * ps[0];
            float e1 = qa1 * pc[1] + qb1 * ps[1];
            float e2 = qa2 * pc[2] + qb2 * ps[2];
            float e3 = qa3 * pc[3] + qb3 * ps[3];
            float4 kv = kb[cur][g];
            dot[g] = kv.x * e0 + kv.y * e1 + kv.z * e2 + kv.w * e3;
            #pragma unroll
            for (int i = 0; i < 4; i++) {
                float c2 = pc[i] * rc[i] + ps[i] * rs[i];
                ps[i] = ps[i] * rc[i] - pc[i] * rs[i];
                pc[i] = c2;
            }
        }

        #pragma unroll
        for (int off = 16; off; off >>= 1) {
            dot[0] += __shfl_xor_sync(0xffffffffu, dot[0], off);
            dot[1] += __shfl_xor_sync(0xffffffffu, dot[1], off);
            dot[2] += __shfl_xor_sync(0xffffffffu, dot[2], off);
            dot[3] += __shfl_xor_sync(0xffffffffu, dot[3], off);
        }

        // mask out-of-range (only token 4095 in split 15's final body)
        #pragma unroll
        for (int g = 0; g < 4; g++)
            if (tA + g * 8 >= NPAST) dot[g] = -1e30f;

        float mn = fmaxf(fmaxf(fmaxf(dot[0], dot[1]), fmaxf(dot[2], dot[3])), m);
        float corr = __expf(m - mn);
        float pA = __expf(dot[0] - mn);
        float pB = __expf(dot[1] - mn);
        float pC = __expf(dot[2] - mn);
        float pD = __expf(dot[3] - mn);
        m = mn;
        l = l * corr + (pA + pB) + (pC + pD);
        float4 vA = vb[cur][0], vB = vb[cur][1], vC = vb[cur][2], vD = vb[cur][3];
        acc.x = acc.x * corr + pA * vA.x + pB * vB.x + pC * vC.x + pD * vD.x;
        acc.y = acc.y * corr + pA * vA.y + pB * vB.y + pC * vC.y + pD * vD.y;
        acc.z = acc.z * corr + pA * vA.z + pB * vB.z + pC * vC.z + pD * vD.z;
        acc.w = acc.w * corr + pA * vA.w + pB * vB.w + pC * vC.w + pD * vD.w;
    }
#undef LOADB

    // ---- cross-warp combine in SMEM ----
    __shared__ float  sm_m[8], sm_l[8];
    __shared__ float4 sm_acc[8][32];
    __shared__ float  red[128];
    __shared__ int    s_last;
    sm_m[warp] = m; sm_l[warp] = l; sm_acc[warp][lane] = acc;
    __syncthreads();

    if (warp == 0) {
        float M = -1e30f;
        #pragma unroll
        for (int w = 0; w < 8; w++) M = fmaxf(M, sm_m[w]);
        float L = 0.f;
        float4 A = make_float4(0.f, 0.f, 0.f, 0.f);
        #pragma unroll
        for (int w = 0; w < 8; w++) {
            float e = __expf(sm_m[w] - M);
            L += e * sm_l[w];
            float4 a = sm_acc[w][lane];
            A.x += e * a.x; A.y += e * a.y; A.z += e * a.z; A.w += e * a.w;
        }
        float* sc = g_scratch + (size_t)bid * SSTRIDE;
        if (lane == 0) { sc[0] = M; sc[1] = L; }
        *(float4*)(sc + 8 + j4) = A;
        __threadfence();                     // make partial visible before count
    }
    __syncthreads();

    if (tid == 0) {
        int old = atomicAdd(&g_cnt[bh], 1);
        s_last = (old == SPLITS - 1);
    }
    __syncthreads();
    if (!s_last) return;

    // ---- last CTA per (b,h): final combine ----
    if (tid == 0) g_cnt[bh] = 0;             // reset for next (graph) launch
    __threadfence();                         // acquire side

    size_t o = (size_t)bh * HD;
    int d = tid;                             // dims handled by threads 0..127

    if (d < HD) red[d] = q[o + d] * kk[o + d];   // same-pos RoPE cancels
    __syncthreads();
    #pragma unroll
    for (int off = 64; off; off >>= 1) {
        if (d < off) red[d] += red[d + off];
        __syncthreads();
    }
    float score = red[0] * SCALE;

    if (d < HD) {
        const float* sc = g_scratch + (size_t)bh * SPLITS * SSTRIDE;
        float M = score;
        #pragma unroll
        for (int s2 = 0; s2 < SPLITS; s2++)
            M = fmaxf(M, __ldcg(sc + s2 * SSTRIDE));
        float w = __expf(score - M);
        float L = w;
        float A = w * vv[o + d];
        #pragma unroll
        for (int s2 = 0; s2 < SPLITS; s2++) {
            float e = __expf(__ldcg(sc + s2 * SSTRIDE) - M);
            L += e * __ldcg(sc + s2 * SSTRIDE + 1);
            A += e * __ldcg(sc + s2 * SSTRIDE + 8 + d);
        }
        out[o + d] = A / L;
    }
}

// ---------------------------------------------------------------------------
extern "C" void kernel_launch(void* const* d_in, const int* in_sizes, int n_in,
                              void* d_out, int out_size)
{
    const float* q  = (const float*)d_in[0];
    const float* k  = (const float*)d_in[1];
    const float* v  = (const float*)d_in[2];
    const float* kc = (const float*)d_in[3];
    const float* vc = (const float*)d_in[4];
    const int*   bt = (const int*)d_in[5];

    int B   = in_sizes[0] / (NH * HD);   // 8
    int bps = in_sizes[5] / B;           // 256

    attn_fused_kernel<<<B * NH * SPLITS, 256>>>(q, k, v, kc, vc, bt,
                                                (float*)d_out, bps);
}